// round 9
// baseline (speedup 1.0000x reference)
#include <cuda_runtime.h>
#include <cuda_bf16.h>
#include <cstdint>
#include <math.h>

#define NDIM 8192
#define RANK 64
#define BM 128
#define BKC 32
#define KQ (NDIM / 2)          // 4096 per K-split
#define NCH (KQ / BKC)         // 128 chunks per CTA
#define QTHREADS 256
#define STAGE 24576            // A 16KB + B 8KB, fp32
#define NSTAGES 4
#define QSMEM (NSTAGES * STAGE + 1024)
#define NCTAS 256

// ---- device scratch (allocation-free rule) ----
__device__ double g_acc[3];                     // [0]=E1, [1]=quad_U, [2]=quad_V
__device__ unsigned int g_done;                 // CTA completion counter
__device__ float  g_Vt[NDIM * RANK];            // V^T fp32 [8192,64] (epilogue)
__device__ float  g_But[RANK * NDIM];           // U^T fp32 [64,8192] (MMA B)
__device__ __nv_bfloat16 g_Ub16[NDIM * RANK];   // U    bf16 [8192,64] (e1)
__device__ __nv_bfloat16 g_Vt16[NDIM * RANK];   // V^T  bf16 [8192,64] (e1)

__device__ __forceinline__ uint32_t smem_u32(const void* p) {
    uint32_t a;
    asm("{ .reg .u64 t; cvta.to.shared.u64 t, %1; cvt.u32.u64 %0, t; }"
        : "=r"(a) : "l"(p));
    return a;
}

// ======================= prep (fused, grid.z selects) =======================
__global__ void prep_kernel(const float* __restrict__ V,
                            const float* __restrict__ U) {
    __shared__ float tile[32][33];
    if (blockIdx.z == 0) {
        int x = blockIdx.x * 32 + threadIdx.x;   // n
        int y = blockIdx.y * 32 + threadIdx.y;   // r
        float v = V[(size_t)y * NDIM + x];
        tile[threadIdx.y][threadIdx.x] = v;
        __syncthreads();
        int n = blockIdx.x * 32 + threadIdx.y;
        int r = blockIdx.y * 32 + threadIdx.x;
        float tv = tile[threadIdx.x][threadIdx.y];
        g_Vt[(size_t)n * RANK + r] = tv;
        g_Vt16[(size_t)n * RANK + r] = __float2bfloat16(tv);
        if (blockIdx.x == 0 && blockIdx.y == 0 && threadIdx.y == 0 &&
            threadIdx.x < 3)
            g_acc[threadIdx.x] = 0.0;
    } else {
        int i0 = blockIdx.x * 32, r0 = blockIdx.y * 32;
        float u = U[(size_t)(i0 + threadIdx.y) * RANK + r0 + threadIdx.x];
        tile[threadIdx.y][threadIdx.x] = u;
        g_Ub16[(size_t)(i0 + threadIdx.y) * RANK + r0 + threadIdx.x] =
            __float2bfloat16(u);
        __syncthreads();
        g_But[(size_t)(r0 + threadIdx.y) * NDIM + i0 + threadIdx.x] =
            tile[threadIdx.x][threadIdx.y];
    }
}

// ============== fused quad (TF32 mma + cp.async pipeline) + e1 ==============
// BM=128, BK=32 fp32. 8 warps; warp wid owns M rows wid*16..+15, full N=64.
// 4-stage cp.async ring; fragments via swizzled ldmatrix (fp32 = 2 b16).
__global__ __launch_bounds__(QTHREADS, 2) void fused_kernel(
    const float* __restrict__ S_U, const float* __restrict__ U,
    const float* __restrict__ S_V, const float* __restrict__ V,
    const float* __restrict__ vals, const int* __restrict__ rows,
    const int* __restrict__ cols, const float* __restrict__ sigma,
    float* __restrict__ out, int nobs) {
    extern __shared__ char dynsmem[];
    __shared__ float wsum[QTHREADS / 32];
    __shared__ float esum[QTHREADS / 32];

    const int t = threadIdx.x;
    const int wid = t >> 5, lane = t & 31;

    const float* S;
    const float* Bp;
    const float* Xf;
    int slot;
    if (blockIdx.z == 0) { S = S_U; Bp = g_But; Xf = U;    slot = 1; }
    else                 { S = S_V; Bp = V;     Xf = g_Vt; slot = 2; }
    const int i0 = blockIdx.x * BM;
    const size_t kbase = (size_t)blockIdx.y * KQ;
    const int ctaid = blockIdx.x + 64 * blockIdx.y + 128 * blockIdx.z; // 0..255

    const uint32_t base = (smem_u32(dynsmem) + 1023u) & ~1023u;

    // ---- cp.async staging coords: granule (row, col) = ((t>>3)+32p, t&7) ----
    const float* a_src = S + (size_t)(i0 + (t >> 3)) * NDIM + kbase +
                         (t & 7) * 4;
    const float* b_src = Bp + (size_t)(t >> 3) * NDIM + kbase + (t & 7) * 4;
    const uint32_t doff = (uint32_t)(t >> 3) * 128 +
                          ((uint32_t)((t & 7) ^ ((t >> 3) & 7)) << 4);

    // ---- ldmatrix lane constants ----
    const int tl = lane >> 3, rl = lane & 7;
    const int agr = tl >> 1;              // A granule parity
    const int bgr = tl & 1;               // B granule parity
    const uint32_t a_rowoff = (uint32_t)(wid * 16 + rl + (tl & 1) * 8) * 128;
    const uint32_t b_rowbase = (uint32_t)(8 * agr + rl) * 128; // + p*2048

    float acc[8][4];
    #pragma unroll
    for (int tn = 0; tn < 8; tn++)
        #pragma unroll
        for (int q = 0; q < 4; q++) acc[tn][q] = 0.f;

    float e1sum = 0.f;

#define ISSUE(cc) do {                                                        \
    uint32_t st = base + ((cc) & 3) * STAGE;                                  \
    size_t ko = (size_t)(cc) * BKC;                                           \
    _Pragma("unroll") for (int p = 0; p < 4; p++) {                           \
        uint32_t d = st + doff + p * 4096;                                    \
        const float* sp = a_src + ko + (size_t)p * 32 * NDIM;                 \
        asm volatile("cp.async.cg.shared.global [%0], [%1], 16;"              \
                     :: "r"(d), "l"(sp));                                     \
    }                                                                         \
    _Pragma("unroll") for (int p = 0; p < 2; p++) {                           \
        uint32_t d = st + 16384 + doff + p * 4096;                            \
        const float* sp = b_src + ko + (size_t)p * 32 * NDIM;                 \
        asm volatile("cp.async.cg.shared.global [%0], [%1], 16;"              \
                     :: "r"(d), "l"(sp));                                     \
    }                                                                         \
} while (0)

#define COMPUTE(st) do {                                                      \
    uint32_t ab = (st), bb = (st) + 16384;                                    \
    _Pragma("unroll") for (int s = 0; s < 4; s++) {                           \
        uint32_t a0, a1, a2, a3;                                              \
        uint32_t aaddr = ab + a_rowoff +                                      \
                         ((uint32_t)((2 * s + agr) ^ rl) << 4);               \
        asm volatile("ldmatrix.sync.aligned.m8n8.x4.shared.b16 "              \
                     "{%0,%1,%2,%3}, [%4];"                                   \
                     : "=r"(a0), "=r"(a1), "=r"(a2), "=r"(a3)                 \
                     : "r"(aaddr));                                           \
        uint32_t bsw = bb + b_rowbase +                                       \
                       ((uint32_t)((2 * s + bgr) ^ rl) << 4);                 \
        _Pragma("unroll") for (int p = 0; p < 4; p++) {                       \
            uint32_t b0, b1, b2, b3;                                          \
            asm volatile("ldmatrix.sync.aligned.m8n8.x4.shared.b16 "          \
                         "{%0,%1,%2,%3}, [%4];"                               \
                         : "=r"(b0), "=r"(b1), "=r"(b2), "=r"(b3)             \
                         : "r"(bsw + p * 2048));                              \
            asm volatile(                                                     \
                "mma.sync.aligned.m16n8k8.row.col.f32.tf32.tf32.f32 "         \
                "{%0,%1,%2,%3}, {%4,%5,%6,%7}, {%8,%9}, {%0,%1,%2,%3};"       \
                : "+f"(acc[2 * p][0]), "+f"(acc[2 * p][1]),                   \
                  "+f"(acc[2 * p][2]), "+f"(acc[2 * p][3])                    \
                : "r"(a0), "r"(a1), "r"(a2), "r"(a3), "r"(b0), "r"(b1));      \
            asm volatile(                                                     \
                "mma.sync.aligned.m16n8k8.row.col.f32.tf32.tf32.f32 "         \
                "{%0,%1,%2,%3}, {%4,%5,%6,%7}, {%8,%9}, {%0,%1,%2,%3};"       \
                : "+f"(acc[2 * p + 1][0]), "+f"(acc[2 * p + 1][1]),           \
                  "+f"(acc[2 * p + 1][2]), "+f"(acc[2 * p + 1][3])            \
                : "r"(a0), "r"(a1), "r"(a2), "r"(a3), "r"(b2), "r"(b3));      \
        }                                                                     \
    }                                                                         \
} while (0)

#define E1_STEP(j) do {                                                       \
    int idx = ctaid * 4096 + (j) * QTHREADS + t;                              \
    if (idx < nobs) {                                                         \
        int r = rows[idx], c = cols[idx];                                     \
        float vv = vals[idx];                                                 \
        const uint4* u4 = (const uint4*)(g_Ub16 + (size_t)r * RANK);          \
        const uint4* v4 = (const uint4*)(g_Vt16 + (size_t)c * RANK);          \
        float s = 0.f;                                                        \
        _Pragma("unroll") for (int q = 0; q < 8; q++) {                       \
            uint4 ua = u4[q];                                                 \
            uint4 vb = v4[q];                                                 \
            const uint32_t* up = &ua.x;                                       \
            const uint32_t* vp = &vb.x;                                       \
            _Pragma("unroll") for (int h = 0; h < 4; h++) {                   \
                float2 fu = __bfloat1622float2(                               \
                    *(const __nv_bfloat162*)&up[h]);                          \
                float2 fv = __bfloat1622float2(                               \
                    *(const __nv_bfloat162*)&vp[h]);                          \
                s = fmaf(fu.x, fv.x, s);                                      \
                s = fmaf(fu.y, fv.y, s);                                      \
            }                                                                 \
        }                                                                     \
        float d = vv - s;                                                     \
        e1sum = fmaf(d, d, e1sum);                                            \
    }                                                                         \
} while (0)

    // prologue: 3 stages in flight
    ISSUE(0);
    asm volatile("cp.async.commit_group;" ::: "memory");
    ISSUE(1);
    asm volatile("cp.async.commit_group;" ::: "memory");
    ISSUE(2);
    asm volatile("cp.async.commit_group;" ::: "memory");

    for (int cc = 0; cc < NCH; cc++) {
        asm volatile("cp.async.wait_group 2;" ::: "memory");
        __syncthreads();
        if ((cc & 7) == 0) E1_STEP(cc >> 3);     // 16 obs per thread
        COMPUTE(base + (cc & 3) * STAGE);
        if (cc + 3 < NCH) ISSUE(cc + 3);
        asm volatile("cp.async.commit_group;" ::: "memory");
    }

    // quad epilogue: partial = sum of D[row][n] * X[row][n]
    const int g = lane >> 2, tg = lane & 3;
    const int r0 = i0 + wid * 16 + g;
    float partial = 0.f;
    #pragma unroll
    for (int tn = 0; tn < 8; tn++) {
        int n = tn * 8 + 2 * tg;
        float2 x0 = *(const float2*)(Xf + (size_t)r0 * RANK + n);
        float2 x1 = *(const float2*)(Xf + (size_t)(r0 + 8) * RANK + n);
        partial = fmaf(acc[tn][0], x0.x, partial);
        partial = fmaf(acc[tn][1], x0.y, partial);
        partial = fmaf(acc[tn][2], x1.x, partial);
        partial = fmaf(acc[tn][3], x1.y, partial);
    }
    #pragma unroll
    for (int o = 16; o; o >>= 1) {
        partial += __shfl_xor_sync(0xffffffffu, partial, o);
        e1sum   += __shfl_xor_sync(0xffffffffu, e1sum, o);
    }
    if (lane == 0) { wsum[wid] = partial; esum[wid] = e1sum; }
    __syncthreads();
    if (t == 0) {
        float s = 0.f, e = 0.f;
        #pragma unroll
        for (int i = 0; i < QTHREADS / 32; i++) { s += wsum[i]; e += esum[i]; }
        atomicAdd(&g_acc[slot], (double)s);
        atomicAdd(&g_acc[0], (double)e);
        __threadfence();
        unsigned int old = atomicAdd(&g_done, 1u);
        if (old == NCTAS - 1) {                  // last CTA finalizes
            __threadfence();
            g_done = 0;                          // reset for next replay
            double e0 = atomicAdd(&g_acc[0], 0.0);
            double e1 = atomicAdd(&g_acc[1], 0.0);
            double e2 = atomicAdd(&g_acc[2], 0.0);
            double s2 = (double)sigma[0] * (double)sigma[0];
            double E = e0 / (2.0 * s2) + 0.5 * (e1 + e2) +
                       (double)nobs * log(s2);
            out[0] = (float)E;
        }
    }
#undef ISSUE
#undef COMPUTE
#undef E1_STEP
}

extern "C" void kernel_launch(void* const* d_in, const int* in_sizes, int n_in,
                              void* d_out, int out_size) {
    const float* vals  = (const float*)d_in[0];
    const int*   rows  = (const int*)d_in[1];
    const int*   cols  = (const int*)d_in[2];
    const float* U     = (const float*)d_in[3];
    const float* V     = (const float*)d_in[4];
    const float* sigma = (const float*)d_in[5];
    const float* S_U   = (const float*)d_in[6];
    const float* S_V   = (const float*)d_in[7];
    int nobs = in_sizes[0];
    float* out = (float*)d_out;

    cudaFuncSetAttribute(fused_kernel,
                         cudaFuncAttributeMaxDynamicSharedMemorySize, QSMEM);

    prep_kernel<<<dim3(NDIM / 32, RANK / 32, 2), dim3(32, 32)>>>(V, U);
    fused_kernel<<<dim3(NDIM / BM, 2, 2), QTHREADS, QSMEM>>>(
        S_U, U, S_V, V, vals, rows, cols, sigma, out, nobs);
}

// round 10
// speedup vs baseline: 1.3896x; 1.3896x over previous
#include <cuda_runtime.h>
#include <cuda_bf16.h>
#include <cstdint>
#include <math.h>

#define NDIM 8192
#define RANK 64
#define BM 128
#define BKC 32
#define KQ (NDIM / 2)          // 4096 per K-split
#define NCH (KQ / BKC)         // 128 chunks per CTA
#define QTHREADS 256
#define ROWB 80                // bf16 smem row stride (bytes), conflict-free
#define A_TILE (BM * ROWB)     // 10240
#define B_TILE (RANK * ROWB)   // 5120
#define STAGEB (A_TILE + B_TILE)
#define QSMEM (3 * STAGEB + 1024)
#define NCTAS 256

// ---- device scratch (allocation-free rule) ----
__device__ double g_acc[3];                     // [0]=E1, [1]=quad_U, [2]=quad_V
__device__ unsigned int g_done;                 // CTA completion counter
__device__ float  g_Vt[NDIM * RANK];            // V^T fp32 [8192,64]
__device__ __nv_bfloat16 g_Bu[RANK * NDIM];     // U^T bf16 [64,8192] (MMA B)
__device__ __nv_bfloat16 g_Bv[RANK * NDIM];     // V   bf16 [64,8192] (MMA B)
__device__ __nv_bfloat16 g_Ub16[NDIM * RANK];   // U    bf16 [8192,64] (e1)
__device__ __nv_bfloat16 g_Vt16[NDIM * RANK];   // V^T  bf16 [8192,64] (e1)

__device__ __forceinline__ uint32_t smem_u32(const void* p) {
    uint32_t a;
    asm("{ .reg .u64 t; cvta.to.shared.u64 t, %1; cvt.u32.u64 %0, t; }"
        : "=r"(a) : "l"(p));
    return a;
}

// ======================= prep (fused, grid.z selects) =======================
__global__ void prep_kernel(const float* __restrict__ V,
                            const float* __restrict__ U) {
    __shared__ float tile[32][33];
    if (blockIdx.z == 0) {
        int x = blockIdx.x * 32 + threadIdx.x;   // n
        int y = blockIdx.y * 32 + threadIdx.y;   // r
        float v = V[(size_t)y * NDIM + x];
        tile[threadIdx.y][threadIdx.x] = v;
        g_Bv[(size_t)y * NDIM + x] = __float2bfloat16(v);
        __syncthreads();
        int n = blockIdx.x * 32 + threadIdx.y;
        int r = blockIdx.y * 32 + threadIdx.x;
        float tv = tile[threadIdx.x][threadIdx.y];
        g_Vt[(size_t)n * RANK + r] = tv;
        g_Vt16[(size_t)n * RANK + r] = __float2bfloat16(tv);
        if (blockIdx.x == 0 && blockIdx.y == 0 && threadIdx.y == 0 &&
            threadIdx.x < 3)
            g_acc[threadIdx.x] = 0.0;
    } else {
        int i0 = blockIdx.x * 32, r0 = blockIdx.y * 32;
        float u = U[(size_t)(i0 + threadIdx.y) * RANK + r0 + threadIdx.x];
        tile[threadIdx.y][threadIdx.x] = u;
        g_Ub16[(size_t)(i0 + threadIdx.y) * RANK + r0 + threadIdx.x] =
            __float2bfloat16(u);
        __syncthreads();
        g_Bu[(size_t)(r0 + threadIdx.y) * NDIM + i0 + threadIdx.x] =
            __float2bfloat16(tile[threadIdx.x][threadIdx.y]);
    }
}

// ============== fused quad (HMMA bf16) + e1 + finalize ==============
// BM=128, BK=32. 8 warps; warp wid owns M rows wid*16..+15, full N=64.
// TWO register staging sets + 3 smem buffers: at iter cc we load chunk cc+2,
// compute chunk cc, store chunk cc+1 (loaded one full iteration earlier),
// giving ~a full chunk of LDG latency coverage. 2 CTAs/SM.
__global__ __launch_bounds__(QTHREADS, 2) void fused_kernel(
    const float* __restrict__ S_U, const float* __restrict__ U,
    const float* __restrict__ S_V, const float* __restrict__ vals,
    const int* __restrict__ rows, const int* __restrict__ cols,
    const float* __restrict__ sigma, float* __restrict__ out, int nobs) {
    extern __shared__ char dynsmem[];
    __shared__ float wsum[QTHREADS / 32];
    __shared__ float esum[QTHREADS / 32];

    const int t = threadIdx.x;
    const int wid = t >> 5, lane = t & 31;

    const float* S;
    const __nv_bfloat16* Bg;
    const float* Xf;
    int slot;
    if (blockIdx.z == 0) { S = S_U; Bg = g_Bu; Xf = U;    slot = 1; }
    else                 { S = S_V; Bg = g_Bv; Xf = g_Vt; slot = 2; }
    const int i0 = blockIdx.x * BM;
    const size_t kbase = (size_t)blockIdx.y * KQ;
    const int ctaid = blockIdx.x + 64 * blockIdx.y + 128 * blockIdx.z; // 0..255

    uint32_t base = (smem_u32(dynsmem) + 1023u) & ~1023u;
    uint32_t cur = base;                 // holds chunk cc (ready)
    uint32_t nx1 = base + STAGEB;        // gets chunk cc+1
    uint32_t nx2 = base + 2 * STAGEB;    // gets chunk cc+2

    // ---- staging coords (BKC=32): A 4 passes x float4; B 1 uint4 ----
    const float* a_base = S + (size_t)(i0 + (t >> 3)) * NDIM + kbase +
                          (t & 7) * 4;
    const uint32_t a_st = (uint32_t)(t >> 3) * ROWB + (t & 7) * 8;
    const __nv_bfloat16* b_base = Bg + (size_t)(t >> 2) * NDIM + kbase +
                                  (t & 3) * 8;
    const uint32_t b_st = (uint32_t)(t >> 2) * ROWB + (t & 3) * 16;

    // ldmatrix lane offsets
    const uint32_t a_lm = (uint32_t)(wid * 16 + (lane & 15)) * ROWB +
                          (lane & 16);
    const uint32_t b_lm = (uint32_t)((lane & 7) + ((lane & 16) >> 1)) * ROWB +
                          ((lane & 8) << 1);

    float acc[8][4];
    #pragma unroll
    for (int tn = 0; tn < 8; tn++)
        #pragma unroll
        for (int q = 0; q < 4; q++) acc[tn][q] = 0.f;

    float e1sum = 0.f;
    float4 rAe[4], rAo[4];
    uint4  rBe, rBo;

#define LOADC(k0, RA, RB) do {                                                \
    _Pragma("unroll") for (int p = 0; p < 4; p++)                             \
        RA[p] = __ldcs((const float4*)(a_base + (k0) +                        \
                                       (size_t)p * 32 * NDIM));               \
    RB = *(const uint4*)(b_base + (k0));                                      \
} while (0)

#define STOREC(buf, RA, RB) do {                                              \
    _Pragma("unroll") for (int p = 0; p < 4; p++) {                           \
        uint32_t lo, hi;                                                      \
        asm("cvt.rn.bf16x2.f32 %0, %1, %2;" : "=r"(lo)                        \
            : "f"(RA[p].y), "f"(RA[p].x));                                    \
        asm("cvt.rn.bf16x2.f32 %0, %1, %2;" : "=r"(hi)                        \
            : "f"(RA[p].w), "f"(RA[p].z));                                    \
        asm volatile("st.shared.v2.b32 [%0], {%1, %2};"                       \
                     :: "r"((buf) + a_st + p * (32 * ROWB)), "r"(lo),         \
                        "r"(hi));                                             \
    }                                                                         \
    asm volatile("st.shared.v4.b32 [%0], {%1, %2, %3, %4};"                   \
                 :: "r"((buf) + A_TILE + b_st), "r"(RB.x), "r"(RB.y),         \
                    "r"(RB.z), "r"(RB.w));                                    \
} while (0)

#define COMPUTE(buf) do {                                                     \
    uint32_t ab = (buf), bb = (buf) + A_TILE;                                 \
    _Pragma("unroll") for (int s = 0; s < 2; s++) {                           \
        uint32_t a[4];                                                        \
        asm volatile("ldmatrix.sync.aligned.m8n8.x4.shared.b16 "              \
                     "{%0,%1,%2,%3}, [%4];"                                   \
                     : "=r"(a[0]), "=r"(a[1]), "=r"(a[2]), "=r"(a[3])         \
                     : "r"(ab + a_lm + s * 32));                              \
        uint32_t b[4][4];                                                     \
        _Pragma("unroll") for (int j = 0; j < 4; j++)                         \
            asm volatile("ldmatrix.sync.aligned.m8n8.x4.shared.b16 "          \
                         "{%0,%1,%2,%3}, [%4];"                               \
                         : "=r"(b[j][0]), "=r"(b[j][1]),                      \
                           "=r"(b[j][2]), "=r"(b[j][3])                       \
                         : "r"(bb + b_lm + j * (16 * ROWB) + s * 32));        \
        _Pragma("unroll") for (int tn = 0; tn < 8; tn++)                      \
            asm volatile("mma.sync.aligned.m16n8k16.row.col.f32.bf16.bf16.f32 " \
                         "{%0,%1,%2,%3}, {%4,%5,%6,%7}, {%8,%9}, "            \
                         "{%0,%1,%2,%3};"                                     \
                         : "+f"(acc[tn][0]), "+f"(acc[tn][1]),                \
                           "+f"(acc[tn][2]), "+f"(acc[tn][3])                 \
                         : "r"(a[0]), "r"(a[1]), "r"(a[2]), "r"(a[3]),        \
                           "r"(b[tn >> 1][(tn & 1) * 2]),                     \
                           "r"(b[tn >> 1][(tn & 1) * 2 + 1]));                \
    }                                                                         \
} while (0)

#define E1_STEP(j) do {                                                       \
    int idx = ctaid * 4096 + (j) * QTHREADS + t;                              \
    if (idx < nobs) {                                                         \
        int r = rows[idx], c = cols[idx];                                     \
        float vv = vals[idx];                                                 \
        const uint4* u4 = (const uint4*)(g_Ub16 + (size_t)r * RANK);          \
        const uint4* v4 = (const uint4*)(g_Vt16 + (size_t)c * RANK);          \
        float s = 0.f;                                                        \
        _Pragma("unroll") for (int q = 0; q < 8; q++) {                       \
            uint4 ua = u4[q];                                                 \
            uint4 vb = v4[q];                                                 \
            const uint32_t* up = &ua.x;                                       \
            const uint32_t* vp = &vb.x;                                       \
            _Pragma("unroll") for (int h = 0; h < 4; h++) {                   \
                float2 fu = __bfloat1622float2(                               \
                    *(const __nv_bfloat162*)&up[h]);                          \
                float2 fv = __bfloat1622float2(                               \
                    *(const __nv_bfloat162*)&vp[h]);                          \
                s = fmaf(fu.x, fv.x, s);                                      \
                s = fmaf(fu.y, fv.y, s);                                      \
            }                                                                 \
        }                                                                     \
        float d = vv - s;                                                     \
        e1sum = fmaf(d, d, e1sum);                                            \
    }                                                                         \
} while (0)

    // prologue: chunk0 -> regs E -> cur buffer; chunk1 -> regs O
    LOADC(0, rAe, rBe);
    STOREC(cur, rAe, rBe);
    LOADC(BKC, rAo, rBo);
    __syncthreads();

    // steady state, two chunks per outer iter:
    //   even step cc:  load(cc+2 -> E) | compute(cur=cc) | store(nx1 <- O=cc+1)
    //   odd step cc+1: load(cc+3 -> O) | compute(nx1)    | store(nx2 <- E=cc+2)
    for (int cc = 0; cc < NCH; cc += 2) {
        if (cc + 2 < NCH) LOADC((size_t)(cc + 2) * BKC, rAe, rBe);
        if ((cc & 15) == 0) E1_STEP(cc >> 4);    // 16 obs per thread... (j<8)
        if ((cc & 15) == 8) E1_STEP((cc >> 4) + 8);
        COMPUTE(cur);
        STOREC(nx1, rAo, rBo);                   // chunk cc+1 (always < NCH)
        __syncthreads();
        if (cc + 3 < NCH) LOADC((size_t)(cc + 3) * BKC, rAo, rBo);
        COMPUTE(nx1);
        if (cc + 2 < NCH) {
            STOREC(nx2, rAe, rBe);
            __syncthreads();
        }
        uint32_t tmp = cur; cur = nx2; nx2 = nx1; nx1 = tmp;
    }

    // quad epilogue: partial = sum of D[row][n] * X[row][n]
    const int g = lane >> 2, tg = lane & 3;
    const int r0 = i0 + wid * 16 + g;
    float partial = 0.f;
    #pragma unroll
    for (int tn = 0; tn < 8; tn++) {
        int n = tn * 8 + 2 * tg;
        float2 x0 = *(const float2*)(Xf + (size_t)r0 * RANK + n);
        float2 x1 = *(const float2*)(Xf + (size_t)(r0 + 8) * RANK + n);
        partial = fmaf(acc[tn][0], x0.x, partial);
        partial = fmaf(acc[tn][1], x0.y, partial);
        partial = fmaf(acc[tn][2], x1.x, partial);
        partial = fmaf(acc[tn][3], x1.y, partial);
    }
    #pragma unroll
    for (int o = 16; o; o >>= 1) {
        partial += __shfl_xor_sync(0xffffffffu, partial, o);
        e1sum   += __shfl_xor_sync(0xffffffffu, e1sum, o);
    }
    if (lane == 0) { wsum[wid] = partial; esum[wid] = e1sum; }
    __syncthreads();
    if (t == 0) {
        float s = 0.f, e = 0.f;
        #pragma unroll
        for (int i = 0; i < QTHREADS / 32; i++) { s += wsum[i]; e += esum[i]; }
        atomicAdd(&g_acc[slot], (double)s);
        atomicAdd(&g_acc[0], (double)e);
        __threadfence();
        unsigned int old = atomicAdd(&g_done, 1u);
        if (old == NCTAS - 1) {                  // last CTA finalizes
            __threadfence();
            g_done = 0;                          // reset for next replay
            double e0 = atomicAdd(&g_acc[0], 0.0);
            double e1 = atomicAdd(&g_acc[1], 0.0);
            double e2 = atomicAdd(&g_acc[2], 0.0);
            double s2 = (double)sigma[0] * (double)sigma[0];
            double E = e0 / (2.0 * s2) + 0.5 * (e1 + e2) +
                       (double)nobs * log(s2);
            out[0] = (float)E;
        }
    }
#undef LOADC
#undef STOREC
#undef COMPUTE
#undef E1_STEP
}

extern "C" void kernel_launch(void* const* d_in, const int* in_sizes, int n_in,
                              void* d_out, int out_size) {
    const float* vals  = (const float*)d_in[0];
    const int*   rows  = (const int*)d_in[1];
    const int*   cols  = (const int*)d_in[2];
    const float* U     = (const float*)d_in[3];
    const float* V     = (const float*)d_in[4];
    const float* sigma = (const float*)d_in[5];
    const float* S_U   = (const float*)d_in[6];
    const float* S_V   = (const float*)d_in[7];
    int nobs = in_sizes[0];
    float* out = (float*)d_out;

    cudaFuncSetAttribute(fused_kernel,
                         cudaFuncAttributeMaxDynamicSharedMemorySize, QSMEM);

    prep_kernel<<<dim3(NDIM / 32, RANK / 32, 2), dim3(32, 32)>>>(V, U);
    fused_kernel<<<dim3(NDIM / BM, 2, 2), QTHREADS, QSMEM>>>(
        S_U, U, S_V, vals, rows, cols, sigma, out, nobs);
}

// round 11
// speedup vs baseline: 1.6786x; 1.2080x over previous
#include <cuda_runtime.h>
#include <cuda_bf16.h>
#include <cstdint>
#include <math.h>

#define NDIM 8192
#define RANK 64
#define BM 128
#define BKC 64
#define KHALF (NDIM / 2)       // 4096
#define NCHH (KHALF / BKC)     // 64 chunks per CTA
#define QTHREADS 256
#define A_TILE (BM * 144)
#define B_TILE (RANK * 144)
#define QSMEM (1024 + 2 * (A_TILE + B_TILE))
#define NCTAS 256

// ---- device scratch (allocation-free rule) ----
__device__ double g_acc[3];                     // [0]=E1, [1]=quad_U, [2]=quad_V
__device__ unsigned int g_done;                 // CTA completion counter
__device__ float  g_Vt[NDIM * RANK];            // V^T fp32 [8192,64]
__device__ __nv_bfloat16 g_Bu[RANK * NDIM];     // U^T bf16 [64,8192] (MMA B)
__device__ __nv_bfloat16 g_Bv[RANK * NDIM];     // V   bf16 [64,8192] (MMA B)
__device__ __nv_bfloat16 g_Ub16[NDIM * RANK];   // U    bf16 [8192,64] (e1)
__device__ __nv_bfloat16 g_Vt16[NDIM * RANK];   // V^T  bf16 [8192,64] (e1)

__device__ __forceinline__ uint32_t smem_u32(const void* p) {
    uint32_t a;
    asm("{ .reg .u64 t; cvta.to.shared.u64 t, %1; cvt.u32.u64 %0, t; }"
        : "=r"(a) : "l"(p));
    return a;
}

// ======================= prep (fused, grid.z selects) =======================
__global__ void prep_kernel(const float* __restrict__ V,
                            const float* __restrict__ U) {
    __shared__ float tile[32][33];
    if (blockIdx.z == 0) {
        int x = blockIdx.x * 32 + threadIdx.x;   // n
        int y = blockIdx.y * 32 + threadIdx.y;   // r
        float v = V[(size_t)y * NDIM + x];
        tile[threadIdx.y][threadIdx.x] = v;
        g_Bv[(size_t)y * NDIM + x] = __float2bfloat16(v);
        __syncthreads();
        int n = blockIdx.x * 32 + threadIdx.y;
        int r = blockIdx.y * 32 + threadIdx.x;
        float tv = tile[threadIdx.x][threadIdx.y];
        g_Vt[(size_t)n * RANK + r] = tv;
        g_Vt16[(size_t)n * RANK + r] = __float2bfloat16(tv);
        if (blockIdx.x == 0 && blockIdx.y == 0 && threadIdx.y == 0 &&
            threadIdx.x < 3)
            g_acc[threadIdx.x] = 0.0;
    } else {
        int i0 = blockIdx.x * 32, r0 = blockIdx.y * 32;
        float u = U[(size_t)(i0 + threadIdx.y) * RANK + r0 + threadIdx.x];
        tile[threadIdx.y][threadIdx.x] = u;
        g_Ub16[(size_t)(i0 + threadIdx.y) * RANK + r0 + threadIdx.x] =
            __float2bfloat16(u);
        __syncthreads();
        g_Bu[(size_t)(r0 + threadIdx.y) * NDIM + i0 + threadIdx.x] =
            __float2bfloat16(tile[threadIdx.x][threadIdx.y]);
    }
}

// ============== fused quad (HMMA bf16) + cooperative e1 + finalize ==========
// Quad engine identical to the 172.8us R7 kernel: BM=128, BK=64, 8 warps,
// 2 smem buffers, 1 sync/chunk, 1-chunk register prefetch, 2 CTAs/SM.
// e1 rebuilt: 8 lanes cooperate per observation (contiguous 16B/lane row
// slices -> 1 L1 line per row instead of 8), shfl-reduced dot.
__global__ __launch_bounds__(QTHREADS, 2) void fused_kernel(
    const float* __restrict__ S_U, const float* __restrict__ U,
    const float* __restrict__ S_V, const float* __restrict__ vals,
    const int* __restrict__ rows, const int* __restrict__ cols,
    const float* __restrict__ sigma, float* __restrict__ out, int nobs) {
    extern __shared__ char dynsmem[];
    __shared__ float wsum[QTHREADS / 32];
    __shared__ float esum[QTHREADS / 32];

    const int t = threadIdx.x;
    const int wid = t >> 5, lane = t & 31;

    const float* S;
    const __nv_bfloat16* Bg;
    const float* Xf;
    int slot;
    if (blockIdx.z == 0) { S = S_U; Bg = g_Bu; Xf = U;    slot = 1; }
    else                 { S = S_V; Bg = g_Bv; Xf = g_Vt; slot = 2; }
    const int i0 = blockIdx.x * BM;
    const size_t kbase = (size_t)blockIdx.y * KHALF;
    const int ctaid = blockIdx.x + 64 * blockIdx.y + 128 * blockIdx.z; // 0..255

    // e1: CTA covers obs [ctaid*4096, +4096); warp covers 512; 4 per step.
    const int e1base = ctaid * 4096 + wid * 512;
    const int lg = lane >> 3;          // obs-group within warp (0..3)
    const int ls = lane & 7;           // slice within row (0..7)

    uint32_t base = (smem_u32(dynsmem) + 1023u) & ~1023u;
    uint32_t buf0 = base;
    uint32_t buf1 = base + (A_TILE + B_TILE);

    // ---- staging: A 8 passes x float4; B 2 passes x uint4 ----
    uint32_t a_sts[8];
    const float* a_ldg[8];
    #pragma unroll
    for (int p = 0; p < 8; p++) {
        int flat = p * QTHREADS + t;
        int row = flat >> 4;
        int c = (flat & 15) * 4;
        a_sts[p] = row * 144 + (flat & 15) * 8;
        a_ldg[p] = S + (size_t)(i0 + row) * NDIM + kbase + c;
    }
    uint32_t b_sts[2];
    const __nv_bfloat16* b_ldg[2];
    #pragma unroll
    for (int p = 0; p < 2; p++) {
        int flat = p * QTHREADS + t;
        int row = flat >> 3;
        int c16 = (flat & 7) * 16;
        b_sts[p] = row * 144 + c16;
        b_ldg[p] = Bg + (size_t)row * NDIM + kbase + c16 / 2;
    }

    const uint32_t a_lm = (uint32_t)(wid * 16 + (lane & 15)) * 144 + (lane & 16);
    const uint32_t b_lm = (uint32_t)((lane & 7) + ((lane & 16) >> 1)) * 144 +
                          ((lane & 8) << 1);

    float acc[8][4];
    #pragma unroll
    for (int tn = 0; tn < 8; tn++)
        #pragma unroll
        for (int q = 0; q < 4; q++) acc[tn][q] = 0.f;

    float e1sum = 0.f;
    float4 rA[8];
    uint4  rB[2];

#define LOADC(k0) do {                                                        \
    _Pragma("unroll") for (int p = 0; p < 8; p++)                             \
        rA[p] = __ldcs((const float4*)(a_ldg[p] + (k0)));                     \
    _Pragma("unroll") for (int p = 0; p < 2; p++)                             \
        rB[p] = *(const uint4*)(b_ldg[p] + (k0));                             \
} while (0)

#define STOREC(buf) do {                                                      \
    _Pragma("unroll") for (int p = 0; p < 8; p++) {                           \
        uint32_t lo, hi;                                                      \
        asm("cvt.rn.bf16x2.f32 %0, %1, %2;" : "=r"(lo)                        \
            : "f"(rA[p].y), "f"(rA[p].x));                                    \
        asm("cvt.rn.bf16x2.f32 %0, %1, %2;" : "=r"(hi)                        \
            : "f"(rA[p].w), "f"(rA[p].z));                                    \
        asm volatile("st.shared.v2.b32 [%0], {%1, %2};"                       \
                     :: "r"((buf) + a_sts[p]), "r"(lo), "r"(hi));             \
    }                                                                         \
    _Pragma("unroll") for (int p = 0; p < 2; p++)                             \
        asm volatile("st.shared.v4.b32 [%0], {%1, %2, %3, %4};"               \
                     :: "r"((buf) + A_TILE + b_sts[p]), "r"(rB[p].x),         \
                        "r"(rB[p].y), "r"(rB[p].z), "r"(rB[p].w));            \
} while (0)

#define COMPUTE(buf) do {                                                     \
    uint32_t ab = (buf), bb = (buf) + A_TILE;                                 \
    _Pragma("unroll") for (int s = 0; s < 4; s++) {                           \
        uint32_t a[4];                                                        \
        asm volatile("ldmatrix.sync.aligned.m8n8.x4.shared.b16 "              \
                     "{%0,%1,%2,%3}, [%4];"                                   \
                     : "=r"(a[0]), "=r"(a[1]), "=r"(a[2]), "=r"(a[3])         \
                     : "r"(ab + a_lm + s * 32));                              \
        uint32_t b[4][4];                                                     \
        _Pragma("unroll") for (int j = 0; j < 4; j++)                         \
            asm volatile("ldmatrix.sync.aligned.m8n8.x4.shared.b16 "          \
                         "{%0,%1,%2,%3}, [%4];"                               \
                         : "=r"(b[j][0]), "=r"(b[j][1]),                      \
                           "=r"(b[j][2]), "=r"(b[j][3])                       \
                         : "r"(bb + b_lm + j * (16 * 144) + s * 32));         \
        _Pragma("unroll") for (int tn = 0; tn < 8; tn++)                      \
            asm volatile("mma.sync.aligned.m16n8k16.row.col.f32.bf16.bf16.f32 " \
                         "{%0,%1,%2,%3}, {%4,%5,%6,%7}, {%8,%9}, "            \
                         "{%0,%1,%2,%3};"                                     \
                         : "+f"(acc[tn][0]), "+f"(acc[tn][1]),                \
                           "+f"(acc[tn][2]), "+f"(acc[tn][3])                 \
                         : "r"(a[0]), "r"(a[1]), "r"(a[2]), "r"(a[3]),        \
                           "r"(b[tn >> 1][(tn & 1) * 2]),                     \
                           "r"(b[tn >> 1][(tn & 1) * 2 + 1]));                \
    }                                                                         \
} while (0)

// cooperative e1: 4 obs per warp per step; 8 lanes per obs, 16B row slice
// each; dot reduced across the 8-lane group via shfl_xor. All lanes execute
// the shuffles (clamped index); accumulation is predicated.
#define E1_STEP4(j) do {                                                      \
    int o = e1base + (j) * 4 + lg;                                            \
    int oc = o < nobs ? o : nobs - 1;                                         \
    int r = rows[oc], c = cols[oc];                                           \
    uint4 ua = *(const uint4*)(g_Ub16 + (size_t)r * RANK + ls * 8);           \
    uint4 vb = *(const uint4*)(g_Vt16 + (size_t)c * RANK + ls * 8);           \
    float s = 0.f;                                                            \
    {                                                                         \
        const uint32_t* up = &ua.x;                                           \
        const uint32_t* vp = &vb.x;                                           \
        _Pragma("unroll") for (int h = 0; h < 4; h++) {                       \
            float2 fu = __bfloat1622float2(*(const __nv_bfloat162*)&up[h]);   \
            float2 fv = __bfloat1622float2(*(const __nv_bfloat162*)&vp[h]);   \
            s = fmaf(fu.x, fv.x, s);                                          \
            s = fmaf(fu.y, fv.y, s);                                          \
        }                                                                     \
    }                                                                         \
    s += __shfl_xor_sync(0xffffffffu, s, 1);                                  \
    s += __shfl_xor_sync(0xffffffffu, s, 2);                                  \
    s += __shfl_xor_sync(0xffffffffu, s, 4);                                  \
    if (ls == 0 && o < nobs) {                                                \
        float d = vals[o] - s;                                                \
        e1sum = fmaf(d, d, e1sum);                                            \
    }                                                                         \
} while (0)

    // prologue
    LOADC(0);
    STOREC(buf0);
    __syncthreads();

    // steady: per chunk — load(cc+1), e1 x2, compute(cc), store(cc+1), 1 sync
    for (int cc = 0; cc < NCHH; cc++) {
        uint32_t cur = (cc & 1) ? buf1 : buf0;
        uint32_t nxt = (cc & 1) ? buf0 : buf1;
        if (cc + 1 < NCHH) LOADC((size_t)(cc + 1) * BKC);
        E1_STEP4(2 * cc);
        E1_STEP4(2 * cc + 1);
        COMPUTE(cur);
        if (cc + 1 < NCHH) {
            STOREC(nxt);
            __syncthreads();
        }
    }

    // quad epilogue: partial = sum of D[row][n] * X[row][n]
    const int g = lane >> 2, tg = lane & 3;
    const int r0 = i0 + wid * 16 + g;
    float partial = 0.f;
    #pragma unroll
    for (int tn = 0; tn < 8; tn++) {
        int n = tn * 8 + 2 * tg;
        float2 x0 = *(const float2*)(Xf + (size_t)r0 * RANK + n);
        float2 x1 = *(const float2*)(Xf + (size_t)(r0 + 8) * RANK + n);
        partial = fmaf(acc[tn][0], x0.x, partial);
        partial = fmaf(acc[tn][1], x0.y, partial);
        partial = fmaf(acc[tn][2], x1.x, partial);
        partial = fmaf(acc[tn][3], x1.y, partial);
    }
    #pragma unroll
    for (int o = 16; o; o >>= 1) {
        partial += __shfl_xor_sync(0xffffffffu, partial, o);
        e1sum   += __shfl_xor_sync(0xffffffffu, e1sum, o);
    }
    if (lane == 0) { wsum[wid] = partial; esum[wid] = e1sum; }
    __syncthreads();
    if (t == 0) {
        float s = 0.f, e = 0.f;
        #pragma unroll
        for (int i = 0; i < QTHREADS / 32; i++) { s += wsum[i]; e += esum[i]; }
        atomicAdd(&g_acc[slot], (double)s);
        atomicAdd(&g_acc[0], (double)e);
        __threadfence();
        unsigned int old = atomicAdd(&g_done, 1u);
        if (old == NCTAS - 1) {                  // last CTA finalizes
            __threadfence();
            g_done = 0;                          // reset for next replay
            double e0 = atomicAdd(&g_acc[0], 0.0);
            double e1 = atomicAdd(&g_acc[1], 0.0);
            double e2 = atomicAdd(&g_acc[2], 0.0);
            double s2 = (double)sigma[0] * (double)sigma[0];
            double E = e0 / (2.0 * s2) + 0.5 * (e1 + e2) +
                       (double)nobs * log(s2);
            out[0] = (float)E;
        }
    }
#undef LOADC
#undef STOREC
#undef COMPUTE
#undef E1_STEP4
}

extern "C" void kernel_launch(void* const* d_in, const int* in_sizes, int n_in,
                              void* d_out, int out_size) {
    const float* vals  = (const float*)d_in[0];
    const int*   rows  = (const int*)d_in[1];
    const int*   cols  = (const int*)d_in[2];
    const float* U     = (const float*)d_in[3];
    const float* V     = (const float*)d_in[4];
    const float* sigma = (const float*)d_in[5];
    const float* S_U   = (const float*)d_in[6];
    const float* S_V   = (const float*)d_in[7];
    int nobs = in_sizes[0];
    float* out = (float*)d_out;

    cudaFuncSetAttribute(fused_kernel,
                         cudaFuncAttributeMaxDynamicSharedMemorySize, QSMEM);

    prep_kernel<<<dim3(NDIM / 32, RANK / 32, 2), dim3(32, 32)>>>(V, U);
    fused_kernel<<<dim3(NDIM / BM, 2, 2), QTHREADS, QSMEM>>>(
        S_U, U, S_V, vals, rows, cols, sigma, out, nobs);
}